// round 1
// baseline (speedup 1.0000x reference)
#include <cuda_runtime.h>

#define AN 360
#define PN 512
#define BN 16
#define IMGN 512
#define IMGSQ (IMGN*IMGN)
#define ROW 20            // padded floats per window row (16 batches + 4 pad)
#define WMAX 64           // max window rows (true max ~46 + margin)

__global__ __launch_bounds__(512, 2)
void radon_bp_kernel(const float* __restrict__ sino,
                     const float* __restrict__ thetas,
                     const float* __restrict__ positions,
                     float* __restrict__ out)
{
    __shared__ float s_cos[AN];
    __shared__ float s_sin[AN];
    __shared__ __align__(16) float s_win[2][WMAX * ROW];

    const int tid = threadIdx.x;
    const int tx  = tid & 31;       // x within tile / window position for loads
    const int ty  = tid >> 5;       // 0..15: y-row pair for compute, batch for loads
    const int x0  = blockIdx.x * 32;
    const int y0  = blockIdx.y * 32;

    const float pos0   = positions[0];
    const float inv_dp = 1.0f / (positions[1] - pos0);

    // stage trig table
    for (int a = tid; a < AN; a += 512) {
        float th = thetas[a];
        s_cos[a] = cosf(th);
        s_sin[a] = sinf(th);
    }

    const float half = (IMGN - 1) * 0.5f;
    const float fx   = (float)(x0 + tx) - half;
    const float fyA  = (float)(y0 + ty) - half;
    const float fyB  = fyA + 16.0f;

    // tile corner coords (centered)
    const float cxm = (float)x0 - half;
    const float cxM = cxm + 31.0f;
    const float cym = (float)y0 - half;
    const float cyM = cym + 31.0f;

    unsigned long long accA[8], accB[8];
    #pragma unroll
    for (int k = 0; k < 8; k++) { accA[k] = 0ull; accB[k] = 0ull; }

    const float* sino_b = sino + (size_t)ty * (AN * PN);  // this thread's batch base (for loads)

    __syncthreads();  // trig visible

    // window bounds for angle a over the whole tile (with +/-1 safety margin)
    auto win_bounds = [&](int a, int& lo, int& W) {
        float c = s_cos[a], s = s_sin[a];
        float px0 = cxm * c, px1 = cxM * c;
        float py0 = cym * s, py1 = cyM * s;
        float tmin = fminf(px0, px1) + fminf(py0, py1);
        float tmax = fmaxf(px0, px1) + fmaxf(py0, py1);
        float fa = (tmin - pos0) * inv_dp;
        float fb = (tmax - pos0) * inv_dp;
        float fmn = fminf(fa, fb), fmx = fmaxf(fa, fb);
        int ilo = __float2int_rd(fmn) - 1;
        int ihi = __float2int_rd(fmx) + 2;
        ilo = max(0, min(PN - 1, ilo));
        ihi = max(0, min(PN - 1, ihi));
        lo = ilo;
        W  = ihi - ilo + 1;
    };

    // prologue: stage window for angle 0 into buffer 0
    int lo_cur, W_cur;
    win_bounds(0, lo_cur, W_cur);
    {
        const float* src = sino_b + lo_cur;   // angle 0
        if (tx      < W_cur) s_win[0][ tx       * ROW + ty] = src[tx];
        if (tx + 32 < W_cur) s_win[0][(tx + 32) * ROW + ty] = src[tx + 32];
    }

    for (int a = 0; a < AN; a++) {
        const int buf = a & 1;
        __syncthreads();  // window[buf] complete; previous compute on buf^1 done

        // prefetch next window into registers (LDG latency overlaps compute)
        int lo_nxt = 0, W_nxt = 0;
        float p0 = 0.0f, p1 = 0.0f;
        if (a + 1 < AN) {
            win_bounds(a + 1, lo_nxt, W_nxt);
            const float* src = sino_b + (size_t)(a + 1) * PN + lo_nxt;
            if (tx      < W_nxt) p0 = src[tx];
            if (tx + 32 < W_nxt) p1 = src[tx + 32];
        }

        // ---- compute angle a from s_win[buf] ----
        {
            const float c = s_cos[a], s = s_sin[a];
            const float xc = fx * c;
            const int hiW = W_cur - 1;
            const float* win = s_win[buf];

            // pixel A
            {
                float fidx = (fmaf(fyA, s, xc) - pos0) * inv_dp;
                float i0f  = floorf(fidx);
                float w    = fidx - i0f;
                int   i0   = (int)i0f;
                float a0 = (i0 >= 0  && i0 <= PN - 1) ? (1.0f - w) : 0.0f;
                float a1 = (i0 >= -1 && i0 <= PN - 2) ? w          : 0.0f;
                int j0 = min(max(i0 - lo_cur,     0), hiW);
                int j1 = min(max(i0 + 1 - lo_cur, 0), hiW);
                unsigned long long A0, A1;
                asm("mov.b64 %0, {%1,%1};" : "=l"(A0) : "f"(a0));
                asm("mov.b64 %0, {%1,%1};" : "=l"(A1) : "f"(a1));
                const ulonglong2* r0 = (const ulonglong2*)(win + j0 * ROW);
                const ulonglong2* r1 = (const ulonglong2*)(win + j1 * ROW);
                #pragma unroll
                for (int k = 0; k < 4; k++) {
                    ulonglong2 g0 = r0[k];
                    ulonglong2 g1 = r1[k];
                    asm("fma.rn.f32x2 %0, %1, %2, %0;" : "+l"(accA[2*k  ]) : "l"(g0.x), "l"(A0));
                    asm("fma.rn.f32x2 %0, %1, %2, %0;" : "+l"(accA[2*k  ]) : "l"(g1.x), "l"(A1));
                    asm("fma.rn.f32x2 %0, %1, %2, %0;" : "+l"(accA[2*k+1]) : "l"(g0.y), "l"(A0));
                    asm("fma.rn.f32x2 %0, %1, %2, %0;" : "+l"(accA[2*k+1]) : "l"(g1.y), "l"(A1));
                }
            }
            // pixel B
            {
                float fidx = (fmaf(fyB, s, xc) - pos0) * inv_dp;
                float i0f  = floorf(fidx);
                float w    = fidx - i0f;
                int   i0   = (int)i0f;
                float a0 = (i0 >= 0  && i0 <= PN - 1) ? (1.0f - w) : 0.0f;
                float a1 = (i0 >= -1 && i0 <= PN - 2) ? w          : 0.0f;
                int j0 = min(max(i0 - lo_cur,     0), hiW);
                int j1 = min(max(i0 + 1 - lo_cur, 0), hiW);
                unsigned long long A0, A1;
                asm("mov.b64 %0, {%1,%1};" : "=l"(A0) : "f"(a0));
                asm("mov.b64 %0, {%1,%1};" : "=l"(A1) : "f"(a1));
                const ulonglong2* r0 = (const ulonglong2*)(win + j0 * ROW);
                const ulonglong2* r1 = (const ulonglong2*)(win + j1 * ROW);
                #pragma unroll
                for (int k = 0; k < 4; k++) {
                    ulonglong2 g0 = r0[k];
                    ulonglong2 g1 = r1[k];
                    asm("fma.rn.f32x2 %0, %1, %2, %0;" : "+l"(accB[2*k  ]) : "l"(g0.x), "l"(A0));
                    asm("fma.rn.f32x2 %0, %1, %2, %0;" : "+l"(accB[2*k  ]) : "l"(g1.x), "l"(A1));
                    asm("fma.rn.f32x2 %0, %1, %2, %0;" : "+l"(accB[2*k+1]) : "l"(g0.y), "l"(A0));
                    asm("fma.rn.f32x2 %0, %1, %2, %0;" : "+l"(accB[2*k+1]) : "l"(g1.y), "l"(A1));
                }
            }
        }

        // store prefetched window for a+1
        if (a + 1 < AN) {
            if (tx      < W_nxt) s_win[buf ^ 1][ tx       * ROW + ty] = p0;
            if (tx + 32 < W_nxt) s_win[buf ^ 1][(tx + 32) * ROW + ty] = p1;
            lo_cur = lo_nxt;
            W_cur  = W_nxt;
        }
    }

    // epilogue: write out[b, 0, y, x]
    const int ox  = x0 + tx;
    const int oyA = y0 + ty;
    const int oyB = oyA + 16;
    #pragma unroll
    for (int m = 0; m < 8; m++) {
        float2 vA = *reinterpret_cast<float2*>(&accA[m]);
        float2 vB = *reinterpret_cast<float2*>(&accB[m]);
        out[(size_t)(2*m    ) * IMGSQ + (size_t)oyA * IMGN + ox] = vA.x;
        out[(size_t)(2*m + 1) * IMGSQ + (size_t)oyA * IMGN + ox] = vA.y;
        out[(size_t)(2*m    ) * IMGSQ + (size_t)oyB * IMGN + ox] = vB.x;
        out[(size_t)(2*m + 1) * IMGSQ + (size_t)oyB * IMGN + ox] = vB.y;
    }
}

extern "C" void kernel_launch(void* const* d_in, const int* in_sizes, int n_in,
                              void* d_out, int out_size)
{
    const float* sino      = (const float*)d_in[0];
    const float* thetas    = (const float*)d_in[1];
    const float* positions = (const float*)d_in[2];
    float* out             = (float*)d_out;

    dim3 grid(IMGN / 32, IMGN / 32);   // 16 x 16 tiles
    radon_bp_kernel<<<grid, 512>>>(sino, thetas, positions, out);
}

// round 2
// speedup vs baseline: 1.1885x; 1.1885x over previous
#include <cuda_runtime.h>

#define AN 360
#define PN 512
#define BN 16
#define IMGN 512
#define IMGSQ (IMGN*IMGN)
#define ROW 20            // floats per window row (16 batches + 4 pad) -> 5 x 16B
#define WMAX 32
#define TPB 128

#define FMA2(acc, g, w) asm("fma.rn.f32x2 %0,%1,%2,%0;" : "+l"(acc) : "l"(g), "l"(w))

__global__ __launch_bounds__(TPB, 6)
void radon_bp(const float* __restrict__ sino,
              const float* __restrict__ thetas,
              const float* __restrict__ positions,
              float* __restrict__ out)
{
    __shared__ float s_cos[AN];
    __shared__ float s_sin[AN];
    __shared__ int   s_meta[AN];
    __shared__ __align__(16) float s_win[2][WMAX * ROW];

    const int tid = threadIdx.x;
    // y-major lane mapping: 8-lane LDS phases vary along y (row delta = s' <= 1 -> no conflicts)
    const int tx = tid >> 4;        // 0..7  : x-pair index
    const int yy = tid & 15;        // 0..15 : y within tile
    const int x0 = blockIdx.x * 16;
    const int y0 = blockIdx.y * 16;

    const float pos0   = positions[0];
    const float inv_dp = 1.0f / (positions[1] - pos0);
    const float pb     = -pos0 * inv_dp;

    const float half = (IMGN - 1) * 0.5f;
    const float cxm = (float)x0 - half;
    const float cxM = cxm + 15.0f;
    const float cym = (float)y0 - half;
    const float cyM = cym + 15.0f;

    // ---- init: premultiplied trig + per-angle window meta ----
    for (int a = tid; a < AN; a += TPB) {
        float th = thetas[a];
        float c = cosf(th) * inv_dp;
        float s = sinf(th) * inv_dp;
        s_cos[a] = c;
        s_sin[a] = s;
        float t0 = c * cxm, t1 = c * cxM;
        float u0 = s * cym, u1 = s * cyM;
        float tmin = fminf(t0, t1) + fminf(u0, u1) + pb;
        float tmax = fmaxf(t0, t1) + fmaxf(u0, u1) + pb;
        int ilo = __float2int_rd(tmin) - 1;
        int ihi = __float2int_rd(tmax) + 2;
        int meta = -1;
        if (ihi >= 0 && ilo <= PN - 1) {   // any tap can be on-detector
            ilo = max(0, min(PN - 1, ilo));
            ihi = max(0, min(PN - 1, ihi));
            if (ihi - ilo < 2) { ilo = max(0, min(ilo, PN - 3)); ihi = ilo + 2; }
            meta = ilo | ((ihi - ilo + 1) << 9);   // lo | (W<<9)
        }
        s_meta[a] = meta;
    }

    const float fxA = (float)(x0 + 2 * tx) - half;
    const float fy  = (float)(y0 + yy) - half;

    unsigned long long accA[8], accB[8];
    #pragma unroll
    for (int m = 0; m < 8; m++) { accA[m] = 0ull; accB[m] = 0ull; }

    // staging role (fixed per thread): warp w loads batches 4w..4w+3, rows = lane
    const int sr  = tid & 31;        // row within window
    const int sbq = tid >> 5;        // batch quad 0..3
    const float* sino_q = sino + (size_t)(4 * sbq) * (AN * PN);
    const size_t BSTR = (size_t)AN * PN;

    __syncthreads();   // trig + meta visible

    // ---- prologue: stage window for angle 0 into buffer 0 ----
    {
        int meta0 = s_meta[0];
        if (meta0 >= 0) {
            int lo = meta0 & 511, W = meta0 >> 9;
            if (sr < W) {
                const float* s0 = sino_q + lo + sr;
                float4 v;
                v.x = s0[0];
                v.y = s0[BSTR];
                v.z = s0[2 * BSTR];
                v.w = s0[3 * BSTR];
                *(float4*)&s_win[0][sr * ROW + 4 * sbq] = v;
            }
        }
    }

    int meta_cur = s_meta[0];

    #pragma unroll 1
    for (int a = 0; a < AN; a++) {
        const int buf = a & 1;

        // prefetch next window (LDG latency overlaps compute)
        int meta_n = (a + 1 < AN) ? s_meta[a + 1] : -1;
        float4 pv;
        bool doSt = false;
        if (meta_n >= 0) {
            int lo_n = meta_n & 511, W_n = meta_n >> 9;
            if (sr < W_n) {
                const float* s0 = sino_q + (size_t)(a + 1) * PN + lo_n + sr;
                pv.x = __ldg(s0);
                pv.y = __ldg(s0 + BSTR);
                pv.z = __ldg(s0 + 2 * BSTR);
                pv.w = __ldg(s0 + 3 * BSTR);
                doSt = true;
            }
        }

        __syncthreads();   // win[buf] complete; prior-iter reads of win[buf^1] done

        if (meta_cur >= 0) {
            const int lo = meta_cur & 511;
            const int W = meta_cur >> 9;
            const float cp = s_cos[a];
            const float sp = s_sin[a];
            const float* win = s_win[buf];

            float base = fmaf(fy, sp, pb);
            float fA = fmaf(fxA, cp, base);
            float fB = fA + cp;

            int im = __float2int_rd(fminf(fA, fB));
            int jb = min(max(im - lo, 0), W - 3);
            int imE = lo + jb;
            const ulonglong2* r0 = (const ulonglong2*)(win + jb * ROW);

            float flA = floorf(fA), flB = floorf(fB);
            float wA = fA - flA,   wB = fB - flB;
            int i0A = (int)flA,    i0B = (int)flB;

            float a0A = ((unsigned)i0A       < PN) ? (1.0f - wA) : 0.0f;
            float a1A = ((unsigned)(i0A + 1) < PN) ? wA          : 0.0f;
            float a0B = ((unsigned)i0B       < PN) ? (1.0f - wB) : 0.0f;
            float a1B = ((unsigned)(i0B + 1) < PN) ? wB          : 0.0f;

            int offA = i0A - imE;
            int offB = i0B - imE;

            float w0A = (offA == 0) ? a0A : ((offA == -1) ? a1A : 0.0f);
            float w1A = (offA == 1) ? a0A : ((offA ==  0) ? a1A : 0.0f);
            float w2A = (offA == 2) ? a0A : ((offA ==  1) ? a1A : 0.0f);
            float w0B = (offB == 0) ? a0B : ((offB == -1) ? a1B : 0.0f);
            float w1B = (offB == 1) ? a0B : ((offB ==  0) ? a1B : 0.0f);
            float w2B = (offB == 2) ? a0B : ((offB ==  1) ? a1B : 0.0f);

            unsigned long long WA0, WA1, WA2, WB0, WB1, WB2;
            asm("mov.b64 %0,{%1,%1};" : "=l"(WA0) : "f"(w0A));
            asm("mov.b64 %0,{%1,%1};" : "=l"(WA1) : "f"(w1A));
            asm("mov.b64 %0,{%1,%1};" : "=l"(WA2) : "f"(w2A));
            asm("mov.b64 %0,{%1,%1};" : "=l"(WB0) : "f"(w0B));
            asm("mov.b64 %0,{%1,%1};" : "=l"(WB1) : "f"(w1B));
            asm("mov.b64 %0,{%1,%1};" : "=l"(WB2) : "f"(w2B));

            #pragma unroll
            for (int k = 0; k < 4; k++) {
                ulonglong2 g0 = r0[k];
                ulonglong2 g1 = r0[k + 5];    // +ROW (20 floats = 5 x 16B)
                ulonglong2 g2 = r0[k + 10];   // +2*ROW
                FMA2(accA[2*k  ], g0.x, WA0);
                FMA2(accA[2*k  ], g1.x, WA1);
                FMA2(accA[2*k  ], g2.x, WA2);
                FMA2(accA[2*k+1], g0.y, WA0);
                FMA2(accA[2*k+1], g1.y, WA1);
                FMA2(accA[2*k+1], g2.y, WA2);
                FMA2(accB[2*k  ], g0.x, WB0);
                FMA2(accB[2*k  ], g1.x, WB1);
                FMA2(accB[2*k  ], g2.x, WB2);
                FMA2(accB[2*k+1], g0.y, WB0);
                FMA2(accB[2*k+1], g1.y, WB1);
                FMA2(accB[2*k+1], g2.y, WB2);
            }
        }

        // store staged window for a+1
        if (doSt) {
            int lo_n = meta_n & 511; (void)lo_n;
            *(float4*)&s_win[buf ^ 1][sr * ROW + 4 * sbq] = pv;
        }
        meta_cur = meta_n;
    }

    // ---- epilogue: out[b, 0, y, x], paired float2 stores ----
    const int xA = x0 + 2 * tx;
    const int yo = y0 + yy;
    float* obase = out + (size_t)yo * IMGN + xA;
    #pragma unroll
    for (int m = 0; m < 8; m++) {
        float2 vA = *reinterpret_cast<float2*>(&accA[m]);
        float2 vB = *reinterpret_cast<float2*>(&accB[m]);
        *(float2*)(obase + (size_t)(2 * m)     * IMGSQ) = make_float2(vA.x, vB.x);
        *(float2*)(obase + (size_t)(2 * m + 1) * IMGSQ) = make_float2(vA.y, vB.y);
    }
}

extern "C" void kernel_launch(void* const* d_in, const int* in_sizes, int n_in,
                              void* d_out, int out_size)
{
    const float* sino      = (const float*)d_in[0];
    const float* thetas    = (const float*)d_in[1];
    const float* positions = (const float*)d_in[2];
    float* out             = (float*)d_out;

    dim3 grid(IMGN / 16, IMGN / 16);   // 32 x 32 = 1024 tiles
    radon_bp<<<grid, TPB>>>(sino, thetas, positions, out);
}